// round 1
// baseline (speedup 1.0000x reference)
#include <cuda_runtime.h>

// Problem constants
#define BS           24
#define C_REP        16
#define H_DIM        320
#define W_DIM        320
#define HW           (H_DIM * W_DIM)         // 102400
#define N_PIX        (BS * HW)               // 2457600
#define NUM_CLASSES  4
#define NUM_MICRO    4
#define NSEG         (NUM_CLASSES * NUM_MICRO)  // 16
#define SEG_STRIDE   17                       // 16 channels + 1 count, padded
#define MOMENTUM     0.99f

// Global scratch: per-segment [16 channel sums, count]
__device__ float g_scratch[NSEG * SEG_STRIDE];

__global__ void zero_scratch_kernel() {
    int t = threadIdx.x;
    if (t < NSEG * SEG_STRIDE) g_scratch[t] = 0.0f;
}

__global__ __launch_bounds__(256) void accum_kernel(
    const float* __restrict__ rep,          // [BS, C_REP, H, W]
    const int* __restrict__ pmi,            // [BS, H, W, NUM_CLASSES]
    const int* __restrict__ target,         // [BS, H, W]
    const int* __restrict__ smask,          // [H, W]
    const unsigned char* __restrict__ cond  // [BS, H, W] (bool, 1 byte)
) {
    __shared__ float s_acc[NSEG * SEG_STRIDE];
    int tid = threadIdx.x;
    for (int i = tid; i < NSEG * SEG_STRIDE; i += blockDim.x)
        s_acc[i] = 0.0f;
    __syncthreads();

    const unsigned stride = gridDim.x * blockDim.x;
    for (unsigned n = blockIdx.x * blockDim.x + tid; n < N_PIX; n += stride) {
        int tgt = target[n];
        bool valid = (tgt != 0);
        if (valid) valid = (cond[n] != 0);
        unsigned hw = n % HW;
        if (valid) valid = (smask[hw] == 1);
        if (valid) {
            unsigned b = n / HW;
            int pidx = pmi[4u * n + (unsigned)tgt];
            int seg = tgt * NUM_MICRO + pidx;
            const float* r = rep + (size_t)b * (C_REP * HW) + hw;

            // Load all 16 channels first for max MLP (independent LDGs)
            float v[C_REP];
            #pragma unroll
            for (int c = 0; c < C_REP; c++)
                v[c] = r[(size_t)c * HW];

            float* base = &s_acc[seg * SEG_STRIDE];
            atomicAdd(&base[C_REP], 1.0f);
            #pragma unroll
            for (int c = 0; c < C_REP; c++)
                atomicAdd(&base[c], v[c]);
        }
    }
    __syncthreads();

    for (int i = tid; i < NSEG * SEG_STRIDE; i += blockDim.x) {
        float val = s_acc[i];
        if (val != 0.0f) atomicAdd(&g_scratch[i], val);
    }
}

__global__ void finalize_kernel(const float* __restrict__ protos,
                                float* __restrict__ out) {
    int i = threadIdx.x;  // 0..255 => seg = i/16, channel = i%16
    if (i >= NSEG * C_REP) return;
    int seg = i >> 4;
    int c = i & 15;
    float cnt = g_scratch[seg * SEG_STRIDE + C_REP];
    float sum = g_scratch[seg * SEG_STRIDE + c];
    float mean = sum / fmaxf(cnt, 1.0f);
    float p = protos[i];
    out[i] = (cnt > 0.0f) ? (MOMENTUM * p + (1.0f - MOMENTUM) * mean) : p;
}

extern "C" void kernel_launch(void* const* d_in, const int* in_sizes, int n_in,
                              void* d_out, int out_size) {
    const float* rep           = (const float*)d_in[0];
    const int* pmi             = (const int*)d_in[1];
    const int* target          = (const int*)d_in[2];
    const int* smask           = (const int*)d_in[3];
    const unsigned char* cond  = (const unsigned char*)d_in[4];
    const float* protos        = (const float*)d_in[5];
    float* out                 = (float*)d_out;

    zero_scratch_kernel<<<1, 512>>>();

    // 8 CTAs per SM x 148 SMs; each thread handles ~8 pixels
    const int block = 256;
    const int grid = 1184;
    accum_kernel<<<grid, block>>>(rep, pmi, target, smask, cond);

    finalize_kernel<<<1, 256>>>(protos, out);
}

// round 2
// speedup vs baseline: 1.1485x; 1.1485x over previous
#include <cuda_runtime.h>

// Problem constants
#define BS           24
#define C_REP        16
#define H_DIM        320
#define W_DIM        320
#define HW           (H_DIM * W_DIM)         // 102400
#define N_PIX        (BS * HW)               // 2457600
#define N_VEC        (N_PIX / 4)             // 614400 4-pixel chunks
#define NUM_CLASSES  4
#define NUM_MICRO    4
#define NSEG         (NUM_CLASSES * NUM_MICRO)  // 16
#define SEG_STRIDE   17                       // 16 channels + 1 count, padded
#define SCRATCH_N    (NSEG * SEG_STRIDE)      // 272
#define MOMENTUM     0.99f

#define GRID_DIM     1184
#define BLOCK_DIM    256

// Global scratch: per-segment [16 channel sums, count]. Zero-init at load;
// the last CTA of every launch re-zeroes it, so every call sees zeros.
__device__ float g_scratch[SCRATCH_N];
__device__ unsigned int g_ticket;   // zero-init; reset by last CTA

__global__ __launch_bounds__(BLOCK_DIM) void fused_kernel(
    const float* __restrict__ rep,          // [BS, C_REP, H, W]
    const int* __restrict__ pmi,            // [BS, H, W, NUM_CLASSES]
    const int* __restrict__ target,         // [BS, H, W]
    const int* __restrict__ smask,          // [H, W]
    const unsigned char* __restrict__ cond, // [BS, H, W] (bool, 1 byte)
    const float* __restrict__ protos,       // [NSEG, C_REP] flat
    float* __restrict__ out                 // [NSEG, C_REP] flat
) {
    __shared__ float s_acc[SCRATCH_N];
    const int tid = threadIdx.x;
    for (int i = tid; i < SCRATCH_N; i += BLOCK_DIM)
        s_acc[i] = 0.0f;
    __syncthreads();

    const int4* __restrict__ target4 = (const int4*)target;
    const uchar4* __restrict__ cond4 = (const uchar4*)cond;
    const int4* __restrict__ smask4  = (const int4*)smask;

    const unsigned stride = GRID_DIM * BLOCK_DIM;
    for (unsigned v = blockIdx.x * BLOCK_DIM + tid; v < N_VEC; v += stride) {
        // 4 consecutive pixels; HW % 4 == 0 so all share the same batch b
        int4 t4  = target4[v];
        uchar4 c4 = cond4[v];
        unsigned hw4 = (4u * v) % HW;          // base hw of the 4 pixels
        int4 m4 = smask4[hw4 / 4 + ((4u * v) / HW) * 0 + (hw4 >> 2) * 0];
        // (hw4/4 indexes smask4 correctly; HW-periodic)
        m4 = smask4[hw4 >> 2];

        int tgt[4]  = {t4.x, t4.y, t4.z, t4.w};
        int msk[4]  = {m4.x, m4.y, m4.z, m4.w};
        unsigned char cn[4] = {c4.x, c4.y, c4.z, c4.w};

        unsigned n0 = 4u * v;
        unsigned b  = n0 / HW;
        const float* rbase = rep + (size_t)b * (C_REP * HW);

        #pragma unroll
        for (int k = 0; k < 4; k++) {
            bool valid = (tgt[k] != 0) && (cn[k] != 0) && (msk[k] == 1);
            if (valid) {
                unsigned n  = n0 + k;
                unsigned hw = hw4 + k;
                int pidx = pmi[4u * n + (unsigned)tgt[k]];
                int seg = tgt[k] * NUM_MICRO + pidx;
                const float* r = rbase + hw;

                float vv[C_REP];
                #pragma unroll
                for (int c = 0; c < C_REP; c++)
                    vv[c] = r[(size_t)c * HW];

                float* base = &s_acc[seg * SEG_STRIDE];
                atomicAdd(&base[C_REP], 1.0f);
                #pragma unroll
                for (int c = 0; c < C_REP; c++)
                    atomicAdd(&base[c], vv[c]);
            }
        }
    }
    __syncthreads();

    // Flush per-CTA partials to global scratch
    for (int i = tid; i < SCRATCH_N; i += BLOCK_DIM) {
        float val = s_acc[i];
        if (val != 0.0f) atomicAdd(&g_scratch[i], val);
    }

    // Last-CTA-done: finalize + reset state for next replay
    __shared__ bool s_last;
    __threadfence();
    if (tid == 0) {
        unsigned t = atomicAdd(&g_ticket, 1u);
        s_last = (t == GRID_DIM - 1);
    }
    __syncthreads();
    if (!s_last) return;

    // i in [0, 256): seg = i/16, channel = i%16. Read via L1-bypass loads
    // (producers wrote through L2 atomics).
    if (tid < NSEG * C_REP) {
        int seg = tid >> 4;
        int c = tid & 15;
        float cnt = __ldcg(&g_scratch[seg * SEG_STRIDE + C_REP]);
        float sum = __ldcg(&g_scratch[seg * SEG_STRIDE + c]);
        float mean = sum / fmaxf(cnt, 1.0f);
        float p = protos[tid];
        out[tid] = (cnt > 0.0f) ? (MOMENTUM * p + (1.0f - MOMENTUM) * mean) : p;
    }
    __syncthreads();   // all reads of g_scratch done before reset

    for (int i = tid; i < SCRATCH_N; i += BLOCK_DIM)
        g_scratch[i] = 0.0f;
    if (tid == 0) g_ticket = 0u;
}

extern "C" void kernel_launch(void* const* d_in, const int* in_sizes, int n_in,
                              void* d_out, int out_size) {
    const float* rep           = (const float*)d_in[0];
    const int* pmi             = (const int*)d_in[1];
    const int* target          = (const int*)d_in[2];
    const int* smask           = (const int*)d_in[3];
    const unsigned char* cond  = (const unsigned char*)d_in[4];
    const float* protos        = (const float*)d_in[5];
    float* out                 = (float*)d_out;

    fused_kernel<<<GRID_DIM, BLOCK_DIM>>>(rep, pmi, target, smask, cond,
                                          protos, out);
}